// round 1
// baseline (speedup 1.0000x reference)
#include <cuda_runtime.h>

// -----------------------------------------------------------------------------
// AdvancedFrequencyDomainIPNLMS — dual-filter frequency-domain AEC.
// One thread per frequency bin (F=129 independent serial chains over 16000
// frames). All filter state lives in registers. 5 blocks x 32 threads so each
// warp gets its own SM/SMSP.
// -----------------------------------------------------------------------------

namespace {

constexpr int FBINS   = 129;
constexpr int KTAPS   = 10;
constexpr int NBATCH  = 8;
constexpr int NTIME   = 2000;
constexpr int NFRAMES = NBATCH * NTIME;   // 16000

__global__ void __launch_bounds__(32, 1)
aec_kernel(const float* __restrict__ mic_r, const float* __restrict__ mic_i,
           const float* __restrict__ ref_r, const float* __restrict__ ref_i,
           const float* __restrict__ fir_r0, const float* __restrict__ fir_i0,
           const float* __restrict__ adf_r0, const float* __restrict__ adf_i0,
           float2* __restrict__ out)
{
    const int f = blockIdx.x * 32 + threadIdx.x;
    if (f >= FBINS) return;

    const int  nb   = (f < 36) ? 10 : 8;     // rows < AEC_MID_CHAN+1 -> K_LOW
    const bool full = (nb == 10);
    const float c1  = 0.25f / (float)nb;     // (1-alpha)/(2*nb), alpha=0.5

    // Register-resident state. Masked taps (k >= nb) are zeroed: the reference
    // never lets them influence any output (mask in estimate/update; clamp is
    // identity on them), so this is output-equivalent and removes the mask
    // from all coefficient-side sums.
    float hr[KTAPS], hi[KTAPS];
    float fr[KTAPS], fi[KTAPS], ar[KTAPS], ai[KTAPS];
#pragma unroll
    for (int k = 0; k < KTAPS; k++) {
        hr[k] = 0.f; hi[k] = 0.f;
        const bool act = (k < nb);
        fr[k] = act ? fir_r0[f * KTAPS + k] : 0.f;
        fi[k] = act ? fir_i0[f * KTAPS + k] : 0.f;
        ar[k] = act ? adf_r0[f * KTAPS + k] : 0.f;
        ai[k] = act ? adf_i0[f * KTAPS + k] : 0.f;
    }
    float mse_in = 1.f, mse_adpt = 1.f, mse_main = 1.f;
    // NOTE: 'power' in the reference is carried but never read -> dropped.

    // Frame order is (t, b): frame n -> t = n/8, b = n%8.
    // Address for [b][t][f] is (b*NTIME + t)*FBINS + f. Walk it incrementally.
    int base = f;       // (t=0, b=0)
    int b    = 0;
    int nlp  = 0;       // n mod 10

    // Software-pipelined input loads (frame 0 preloaded).
    float m_r = mic_r[base], m_i = mic_i[base];
    float r_r = ref_r[base], r_i = ref_i[base];

#pragma unroll 1
    for (int n = 0; n < NFRAMES; n++) {
        const int obase = base;

        // ---- advance & prefetch next frame (final iteration prefetches a
        //      valid in-bounds dummy address: t-wrap lands at 2000*129+f).
        if (b == NBATCH - 1) { b = 0; base += FBINS - (NBATCH - 1) * NTIME * FBINS; }
        else                 { b++;   base += NTIME * FBINS; }
        const float nm_r = mic_r[base], nm_i = mic_i[base];
        const float nr_r = ref_r[base], nr_i = ref_i[base];

        // ---- history shift-in of new reference frame
#pragma unroll
        for (int k = KTAPS - 1; k > 0; k--) { hr[k] = hr[k - 1]; hi[k] = hi[k - 1]; }
        hr[0] = r_r; hi[0] = r_i;

        // ---- dual estimates: er = sum c_r*h_r + c_i*h_i ; ei = sum c_r*h_i - c_i*h_r
        float fer = 0.f, fei = 0.f, aer = 0.f, aei = 0.f;
#pragma unroll
        for (int k = 0; k < KTAPS; k++) {
            fer = fmaf(fr[k], hr[k], fmaf( fi[k], hi[k], fer));
            fei = fmaf(fr[k], hi[k], fmaf(-fi[k], hr[k], fei));
            aer = fmaf(ar[k], hr[k], fmaf( ai[k], hi[k], aer));
            aei = fmaf(ar[k], hi[k], fmaf(-ai[k], hr[k], aei));
        }

        const float ferr_r = m_r - fer, ferr_i = m_i - fei;
        const float aerr_r = m_r - aer, aerr_i = m_i - aei;
        const float f_pow  = fmaf(ferr_r, ferr_r, ferr_i * ferr_i);
        const float a_pow  = fmaf(aerr_r, aerr_r, aerr_i * aerr_i);
        const bool  sel    = (f_pow >= a_pow);
        const float err_r  = sel ? aerr_r : ferr_r;
        const float err_i  = sel ? aerr_i : ferr_i;

        // ---- MSE smoothing + control flags
        mse_in   = fmaf(0.97f, mse_in,   (1.0f - 0.97f) * fmaf(m_r, m_r, m_i * m_i));
        mse_main = fmaf(0.97f, mse_main, (1.0f - 0.97f) * f_pow);
        mse_adpt = fmaf(0.97f, mse_adpt, (1.0f - 0.97f) * a_pow);
        const bool dt  = (mse_adpt > mse_in * 8.0f);
        const bool rec = (mse_in > mse_main * 8.0f) && (mse_main < 0.5f * mse_adpt);

        // ---- IPNLMS update of the background (ADF) filter, gated by !dt.
        // When dt: gate=0 -> ur=ui=clip(0)=0, coefficients unchanged, and the
        // clamp is provably a no-op (mag already <= ~2) -> skip everything.
        if (!dt) {
            float s = 1e-10f;
            float mag2[KTAPS];
#pragma unroll
            for (int k = 0; k < KTAPS; k++) {
                mag2[k] = fmaf(ar[k], ar[k], ai[k] * ai[k]);
                s += mag2[k];                    // zeros beyond nb contribute 0
            }
            float tot = 0.f;                     // sum over ACTIVE taps only
#pragma unroll
            for (int k = 0; k < 8; k++)
                tot = fmaf(hr[k], hr[k], fmaf(hi[k], hi[k], tot));
            if (full) {
                tot = fmaf(hr[8], hr[8], fmaf(hi[8], hi[8], tot));
                tot = fmaf(hr[9], hr[9], fmaf(hi[9], hi[9], tot));
            }
            const float mu_n  = 0.5f / ((tot + 1e-8f) + 1e-10f);
            const float inv_s = 1.5f / s;        // (1+alpha)/s

#pragma unroll
            for (int k = 0; k < 8; k++) {
                const float kl = fmaf(inv_s, mag2[k], c1);
                const float mk = mu_n * kl;
                const float pr = fmaf(hr[k], aerr_r,  hi[k] * aerr_i);
                const float pi = fmaf(hi[k], aerr_r, -hr[k] * aerr_i);
                ar[k] += fminf(fmaxf(mk * pr, -0.01f), 0.01f);
                ai[k] += fminf(fmaxf(mk * pi, -0.01f), 0.01f);
            }
            if (full) {
#pragma unroll
                for (int k = 8; k < 10; k++) {
                    const float kl = fmaf(inv_s, mag2[k], c1);
                    const float mk = mu_n * kl;
                    const float pr = fmaf(hr[k], aerr_r,  hi[k] * aerr_i);
                    const float pi = fmaf(hi[k], aerr_r, -hr[k] * aerr_i);
                    ar[k] += fminf(fmaxf(mk * pr, -0.01f), 0.01f);
                    ai[k] += fminf(fmaxf(mk * pi, -0.01f), 0.01f);
                }
            }

            // ---- magnitude clamp (mag > 2 <=> mag^2+1e-10 > 4). Common case:
            // nothing exceeds 2 -> one max-reduce + branch keeps the MUFU.RSQ
            // chain off the steady-state path.
            float c2[KTAPS];
            float mx = 0.f;
#pragma unroll
            for (int k = 0; k < KTAPS; k++) {
                c2[k] = fmaf(ar[k], ar[k], fmaf(ai[k], ai[k], 1e-10f));
                mx = fmaxf(mx, c2[k]);
            }
            if (mx > 4.0f) {
#pragma unroll
                for (int k = 0; k < KTAPS; k++) {
                    if (c2[k] > 4.0f) {
                        const float sc = 2.0f * rsqrtf(c2[k]);
                        ar[k] *= sc; ai[k] *= sc;
                    }
                }
            }
        }

        // ---- copy adaptive -> main where adaptive wins, then recovery
#pragma unroll
        for (int k = 0; k < KTAPS; k++) {
            fr[k] = sel ? ar[k] : fr[k];
            fi[k] = sel ? ai[k] : fi[k];
        }
#pragma unroll
        for (int k = 0; k < KTAPS; k++) {
            ar[k] = rec ? fr[k] : ar[k];
            ai[k] = rec ? fi[k] : ai[k];
        }

        // ---- output (spectral-subtraction NLP every 10th frame; warp-uniform)
        float o_r = err_r, o_i = err_i;
        if (nlp == 0) {
            const float echo_r = sel ? aer : fer;
            const float echo_i = sel ? aei : fei;
            const float em = sqrtf(fmaf(err_r, err_r, fmaf(err_i, err_i, 1e-12f)));
            const float qm = sqrtf(fmaf(echo_r, echo_r, echo_i * echo_i));
            const float supp = fmaxf(em - 1.5f * qm, 0.01f * em);
            const float g = supp / em;
            o_r = g * err_r; o_i = g * err_i;
        }
        nlp = (nlp == 9) ? 0 : (nlp + 1);

        out[obase] = make_float2(o_r, o_i);

        m_r = nm_r; m_i = nm_i; r_r = nr_r; r_i = nr_i;
    }
}

} // namespace

extern "C" void kernel_launch(void* const* d_in, const int* in_sizes, int n_in,
                              void* d_out, int out_size)
{
    (void)in_sizes; (void)n_in; (void)out_size;
    aec_kernel<<<(FBINS + 31) / 32, 32>>>(
        (const float*)d_in[0], (const float*)d_in[1],
        (const float*)d_in[2], (const float*)d_in[3],
        (const float*)d_in[4], (const float*)d_in[5],
        (const float*)d_in[6], (const float*)d_in[7],
        (float2*)d_out);
}

// round 4
// speedup vs baseline: 2.3504x; 2.3504x over previous
#include <cuda_runtime.h>

// -----------------------------------------------------------------------------
// AdvancedFrequencyDomainIPNLMS — dual-filter frequency-domain AEC.
// Round 3: tap-parallel layout (resubmit of R2 algorithm; the only exotic
// construct, shfl_up, re-encoded as explicit-source shfl in case the prior
// container failures were source-correlated).
// 4 lanes per frequency bin; lane sub owns contiguous taps (3,3,2,2).
// Cross-lane sums via 4-lane butterfly shuffles; history shift passes one
// boundary element per lane. 17 blocks x 32 threads, one warp per SM.
// -----------------------------------------------------------------------------

namespace {

constexpr int FBINS   = 129;
constexpr int NBATCH  = 8;
constexpr int NTIME   = 2000;
constexpr int NFRAMES = NBATCH * NTIME;   // 16000
constexpr unsigned FULL = 0xffffffffu;

__device__ __forceinline__ float red4(float v) {
    // sum across the aligned 4-lane group (xor 1, xor 2 stay in-group)
    v += __shfl_xor_sync(FULL, v, 1);
    v += __shfl_xor_sync(FULL, v, 2);
    return v;
}

__global__ void __launch_bounds__(32, 1)
aec_kernel(const float* __restrict__ mic_r, const float* __restrict__ mic_i,
           const float* __restrict__ ref_r, const float* __restrict__ ref_i,
           const float* __restrict__ fir_r0, const float* __restrict__ fir_i0,
           const float* __restrict__ adf_r0, const float* __restrict__ adf_i0,
           float2* __restrict__ out)
{
    const int lane = threadIdx.x;
    const int sub  = lane & 3;                    // lane within bin-group
    const int bin  = blockIdx.x * 8 + (lane >> 2);
    const int f    = (bin < FBINS) ? bin : (FBINS - 1);  // dummy groups shadow bin 128
    const bool writer = (sub == 0) && (bin < FBINS);

    const int   nb  = (f < 36) ? 10 : 8;          // K_LOW below AEC_MID_CHAN+1
    const float c1  = 0.25f / (float)nb;          // (1-alpha)/(2*nb), alpha=0.5

    // Contiguous tap slices: lane sub owns taps [off, off+cnt)
    const int off = (sub == 0) ? 0 : (sub == 1) ? 3 : (sub == 2) ? 6 : 8;
    const int cnt = (sub < 2) ? 3 : 2;

    // Per-lane state (3 slots; slot >= cnt is dead weight kept at zero).
    // Masked taps (k >= nb) hold coef == 0 forever (updates gated by actf),
    // output-equivalent to the reference's BLOCK_MASK.
    float actf[3];
    float hr[3] = {0.f, 0.f, 0.f}, hi[3] = {0.f, 0.f, 0.f};
    float frl[3], fil[3], arl[3], ail[3];
#pragma unroll
    for (int j = 0; j < 3; j++) {
        const int  k   = off + j;
        const bool act = (j < cnt) && (k < nb);
        actf[j] = act ? 1.f : 0.f;
        frl[j] = act ? fir_r0[f * 10 + k] : 0.f;
        fil[j] = act ? fir_i0[f * 10 + k] : 0.f;
        arl[j] = act ? adf_r0[f * 10 + k] : 0.f;
        ail[j] = act ? adf_i0[f * 10 + k] : 0.f;
    }
    float mse_in = 1.f, mse_adpt = 1.f, mse_main = 1.f;

    // Frame order (t, b): address for [b][t][f] is (b*NTIME + t)*FBINS + f.
    int base = f, b = 0, nlp = 0;
    float m_r = mic_r[base], m_i = mic_i[base];
    float r_r = ref_r[base], r_i = ref_i[base];

#pragma unroll 1
    for (int n = 0; n < NFRAMES; n++) {
        const int obase = base;

        // ---- advance & prefetch next frame (last iter prefetches a valid
        //      in-bounds address past the used region: (t=2000,b=0) < size)
        if (b == NBATCH - 1) { b = 0; base += FBINS - (NBATCH - 1) * NTIME * FBINS; }
        else                 { b++;   base += NTIME * FBINS; }
        const float nm_r = mic_r[base], nm_i = mic_i[base];
        const float nr_r = ref_r[base], nr_i = ref_i[base];

        // ---- history shift-in. Each lane exports its last ACTIVE-slice
        // element; lane sub imports from lane sub-1 (explicit source lane;
        // sub==0 reads lane 3 of the previous group but discards it and takes
        // the fresh reference sample instead).
        const float last_r = (sub < 2) ? hr[2] : hr[1];
        const float last_i = (sub < 2) ? hi[2] : hi[1];
        const int   src    = (lane - 1) & 31;
        const float inc_r  = __shfl_sync(FULL, last_r, src);
        const float inc_i  = __shfl_sync(FULL, last_i, src);
        hr[2] = hr[1]; hr[1] = hr[0]; hr[0] = (sub == 0) ? r_r : inc_r;
        hi[2] = hi[1]; hi[1] = hi[0]; hi[0] = (sub == 0) ? r_i : inc_i;

        // ---- per-lane partial sums (estimates + update statistics together
        //      so the two shuffle-reduction chains overlap)
        float fer = 0.f, fei = 0.f, aer = 0.f, aei = 0.f;
        float sp = 0.f, tp = 0.f;
        float mg2[3];
#pragma unroll
        for (int j = 0; j < 3; j++) {
            fer = fmaf(frl[j], hr[j], fmaf( fil[j], hi[j], fer));
            fei = fmaf(frl[j], hi[j], fmaf(-fil[j], hr[j], fei));
            aer = fmaf(arl[j], hr[j], fmaf( ail[j], hi[j], aer));
            aei = fmaf(arl[j], hi[j], fmaf(-ail[j], hr[j], aei));
            mg2[j] = fmaf(arl[j], arl[j], ail[j] * ail[j]);
            sp += mg2[j];                               // zero-coef slots add 0
            const float t = fmaf(hr[j], hr[j], hi[j] * hi[j]);
            tp = fmaf(actf[j], t, tp);                  // tot over ACTIVE taps
        }
        fer = red4(fer); fei = red4(fei);
        aer = red4(aer); aei = red4(aei);
        const float s   = red4(sp) + 1e-10f;
        const float tot = red4(tp);

        // ---- errors, selection, MSE recursions, control flags (replicated)
        const float ferr_r = m_r - fer, ferr_i = m_i - fei;
        const float aerr_r = m_r - aer, aerr_i = m_i - aei;
        const float f_pow  = fmaf(ferr_r, ferr_r, ferr_i * ferr_i);
        const float a_pow  = fmaf(aerr_r, aerr_r, aerr_i * aerr_i);
        const bool  sel    = (f_pow >= a_pow);
        const float err_r  = sel ? aerr_r : ferr_r;
        const float err_i  = sel ? aerr_i : ferr_i;

        mse_in   = fmaf(0.97f, mse_in,   0.03f * fmaf(m_r, m_r, m_i * m_i));
        mse_main = fmaf(0.97f, mse_main, 0.03f * f_pow);
        mse_adpt = fmaf(0.97f, mse_adpt, 0.03f * a_pow);
        const bool dt  = (mse_adpt > mse_in * 8.0f);
        const bool rec = (mse_in > mse_main * 8.0f) && (mse_main < 0.5f * mse_adpt);

        // ---- IPNLMS update of ADF filter (branchless dt gate folded into mu_n;
        //      gate*clip(x) == clip(gate*x) for gate in {0,1})
        float mu_n = __fdividef(0.5f, (tot + 1e-8f) + 1e-10f);
        mu_n = dt ? 0.f : mu_n;
        const float inv_s = __fdividef(1.5f, s);        // (1+alpha)/s

#pragma unroll
        for (int j = 0; j < 3; j++) {
            const float kl = fmaf(inv_s, mg2[j], c1);
            const float mk = (mu_n * kl) * actf[j];
            const float pr = fmaf(hr[j], aerr_r,   hi[j] * aerr_i);
            const float pi = fmaf(hi[j], aerr_r, -(hr[j] * aerr_i));
            arl[j] += fminf(fmaxf(mk * pr, -0.01f), 0.01f);
            ail[j] += fminf(fmaxf(mk * pi, -0.01f), 0.01f);
        }

        // ---- magnitude clamp (mag > 2 <=> mag^2 + 1e-10 > 4); fast path is a
        //      per-lane max + rare divergent branch, no shuffles inside.
        {
            float c2[3], mx = 0.f;
#pragma unroll
            for (int j = 0; j < 3; j++) {
                c2[j] = fmaf(arl[j], arl[j], fmaf(ail[j], ail[j], 1e-10f));
                mx = fmaxf(mx, c2[j]);
            }
            if (mx > 4.0f) {
#pragma unroll
                for (int j = 0; j < 3; j++) {
                    if (c2[j] > 4.0f) {
                        const float sc = 2.0f * rsqrtf(c2[j]);
                        arl[j] *= sc; ail[j] *= sc;
                    }
                }
            }
        }

        // ---- copy adaptive -> main where adaptive wins, then recovery
#pragma unroll
        for (int j = 0; j < 3; j++) {
            frl[j] = sel ? arl[j] : frl[j];
            fil[j] = sel ? ail[j] : fil[j];
        }
#pragma unroll
        for (int j = 0; j < 3; j++) {
            arl[j] = rec ? frl[j] : arl[j];
            ail[j] = rec ? fil[j] : ail[j];
        }

        // ---- output (NLP every 10th frame; warp-uniform branch)
        float o_r = err_r, o_i = err_i;
        if (nlp == 0) {
            const float echo_r = sel ? aer : fer;
            const float echo_i = sel ? aei : fei;
            const float em = sqrtf(fmaf(err_r, err_r, fmaf(err_i, err_i, 1e-12f)));
            const float qm = sqrtf(fmaf(echo_r, echo_r, echo_i * echo_i));
            const float supp = fmaxf(em - 1.5f * qm, 0.01f * em);
            const float g = __fdividef(supp, em);
            o_r = g * err_r; o_i = g * err_i;
        }
        nlp = (nlp == 9) ? 0 : (nlp + 1);

        if (writer) out[obase] = make_float2(o_r, o_i);

        m_r = nm_r; m_i = nm_i; r_r = nr_r; r_i = nr_i;
    }
}

} // namespace

extern "C" void kernel_launch(void* const* d_in, const int* in_sizes, int n_in,
                              void* d_out, int out_size)
{
    (void)in_sizes; (void)n_in; (void)out_size;
    aec_kernel<<<17, 32>>>(
        (const float*)d_in[0], (const float*)d_in[1],
        (const float*)d_in[2], (const float*)d_in[3],
        (const float*)d_in[4], (const float*)d_in[5],
        (const float*)d_in[6], (const float*)d_in[7],
        (float2*)d_out);
}